// round 16
// baseline (speedup 1.0000x reference)
#include <cuda_runtime.h>
#include <cuda_fp16.h>
#include <math.h>
#include <stdint.h>

#define T_DIM 8192
#define D_DIM 512
#define RSPLIT 45                 // row-block split: A = [0,45), B = [45,64)

// Scratch (allocation-free rule: __device__ globals)
__device__ __half g_hnorm[T_DIM * D_DIM];
__device__ __half g_q[T_DIM * D_DIM];
__device__ __half g_k[T_DIM * D_DIM];
__device__ __half g_vt[T_DIM * D_DIM];            // V'^T : [d][T], V' = hn @ (Wo Wv)^T
__device__ float  g_avp[4][T_DIM * D_DIM];        // PV split-K partials (fp32)
__device__ __half g_wr[4][D_DIM * D_DIM];         // fp16 weights: q, k, (W'), o
__device__ __half g_wvt[D_DIM * D_DIM];           // Wv^T fp16
__device__ __half g_S[(size_t)T_DIM * T_DIM];     // 128 MB score/prob matrix

// ===========================================================================
// Helpers
// ===========================================================================
__device__ __forceinline__ uint32_t smem_u32(const void* p) {
    uint32_t a;
    asm("{ .reg .u64 t; cvta.to.shared.u64 t, %1; cvt.u32.u64 %0, t; }" : "=r"(a) : "l"(p));
    return a;
}
__device__ __forceinline__ uint32_t pack_h2(float a, float b) {
    __half2 h = __floats2half2_rn(a, b);
    return *(uint32_t*)&h;
}
#define SW128(o) ((o) ^ ((((uint32_t)(o)) >> 3) & 0x70))
#define NEG_BIG (-60000.0f)
#define SM_SHIFT 20.0f          // uniform softmax shift (scores bounded << 88-20)

#define CP_ASYNC16(dst, src) \
    asm volatile("cp.async.cg.shared.global [%0], [%1], 16;" :: "r"(dst), "l"(src) : "memory")
#define CP_COMMIT() asm volatile("cp.async.commit_group;" ::: "memory")
#define CP_WAIT1()  asm volatile("cp.async.wait_group 1;" ::: "memory")

__device__ __forceinline__ void ldsm_x4(uint32_t& r0, uint32_t& r1, uint32_t& r2, uint32_t& r3,
                                        uint32_t addr) {
    asm volatile("ldmatrix.sync.aligned.m8n8.x4.shared.b16 {%0,%1,%2,%3}, [%4];"
                 : "=r"(r0), "=r"(r1), "=r"(r2), "=r"(r3) : "r"(addr));
}

// fp16 MMA, fp32 accumulate: m16n8k16
__device__ __forceinline__ void mma_f16(float* c, const uint32_t* a, const uint32_t* b) {
    asm volatile(
        "mma.sync.aligned.m16n8k16.row.col.f32.f16.f16.f32 "
        "{%0,%1,%2,%3}, {%4,%5,%6,%7}, {%8,%9}, {%0,%1,%2,%3};"
        : "+f"(c[0]), "+f"(c[1]), "+f"(c[2]), "+f"(c[3])
        : "r"(a[0]), "r"(a[1]), "r"(a[2]), "r"(a[3]),
          "r"(b[0]), "r"(b[1]));
}

// ===========================================================================
// LayerNorm (one block/row, 128 thr) -> fp16 output.
// Blocks 0..1023 additionally round the 4 weight matrices into g_wr (fp16).
// ===========================================================================
__global__ void ln_kernel(const float* __restrict__ h,
                          const float* __restrict__ w,
                          const float* __restrict__ b,
                          __half* __restrict__ out,
                          const float* __restrict__ w0,
                          const float* __restrict__ w1,
                          const float* __restrict__ w2,
                          const float* __restrict__ w3,
                          __half* __restrict__ wr)
{
    int row = blockIdx.x;
    int t = threadIdx.x;

    if (row < 1024) {
        #pragma unroll
        for (int j = 0; j < 2; j++) {
            int idx = row * 256 + j * 128 + t;      // float4 index, 0..262143
            int mat = idx >> 16;
            int off = idx & 65535;
            const float* src = (mat == 0) ? w0 : (mat == 1) ? w1
                             : (mat == 2) ? w2 : w3;
            float4 v = ((const float4*)src)[off];
            uint2 u;
            u.x = pack_h2(v.x, v.y);
            u.y = pack_h2(v.z, v.w);
            ((uint2*)wr)[(size_t)mat * 65536 + off] = u;
        }
    }

    const float4* hr = (const float4*)(h + (size_t)row * D_DIM);
    float4 x = hr[t];
    float s  = x.x + x.y + x.z + x.w;
    float ss = x.x * x.x + x.y * x.y + x.z * x.z + x.w * x.w;

    #pragma unroll
    for (int o = 16; o; o >>= 1) {
        s  += __shfl_xor_sync(0xffffffffu, s,  o);
        ss += __shfl_xor_sync(0xffffffffu, ss, o);
    }
    __shared__ float red[2][4];
    int lane = t & 31, warp = t >> 5;
    if (lane == 0) { red[0][warp] = s; red[1][warp] = ss; }
    __syncthreads();
    float a = red[0][0] + red[0][1] + red[0][2] + red[0][3];
    float c = red[1][0] + red[1][1] + red[1][2] + red[1][3];
    float mean = a * (1.0f / D_DIM);
    float var  = c * (1.0f / D_DIM) - mean * mean;
    float rstd = rsqrtf(var + 1e-5f);

    float4 wv = ((const float4*)w)[t];
    float4 bv = ((const float4*)b)[t];
    uint2 u;
    u.x = pack_h2((x.x - mean) * rstd * wv.x + bv.x,
                  (x.y - mean) * rstd * wv.y + bv.y);
    u.y = pack_h2((x.z - mean) * rstd * wv.z + bv.z,
                  (x.w - mean) * rstd * wv.w + bv.w);
    *(uint2*)(out + (size_t)row * D_DIM + t * 4) = u;
}

// ===========================================================================
// Wv transpose: wvt[j][i] = fp16(Wv[i][j])  (512x512)
// ===========================================================================
__global__ void wv_transpose(const float* __restrict__ wv, __half* __restrict__ wvt)
{
    __shared__ float tile[32][33];
    int x0 = blockIdx.x * 32;
    int y0 = blockIdx.y * 32;
    int tx = threadIdx.x & 31, ty = threadIdx.x >> 5;   // 32 x 8
    #pragma unroll
    for (int i = 0; i < 32; i += 8)
        tile[ty + i][tx] = wv[(size_t)(y0 + ty + i) * D_DIM + x0 + tx];
    __syncthreads();
    #pragma unroll
    for (int i = 0; i < 32; i += 8)
        wvt[(size_t)(x0 + ty + i) * D_DIM + y0 + tx] = __float2half_rn(tile[tx][ty + i]);
}

// ===========================================================================
// Final: out = sum of 4 PV partials (z=0 partial already contains +h)
// elem4_off = float4 offset of this half's row range.
// ===========================================================================
__global__ void reduce_out(const float* __restrict__ avp,
                           float* __restrict__ out, int elem4_off)
{
    int i = elem4_off + blockIdx.x * 256 + threadIdx.x;
    const size_t Np = (size_t)T_DIM * D_DIM / 4;
    const float4* p = (const float4*)avp;
    float4 a = p[i], b = p[i + Np], c = p[i + 2 * Np], d = p[i + 3 * Np];
    float4 o;
    o.x = (a.x + b.x) + (c.x + d.x);
    o.y = (a.y + b.y) + (c.y + d.y);
    o.z = (a.z + b.z) + (c.z + d.z);
    o.w = (a.w + b.w) + (c.w + d.w);
    ((float4*)out)[i] = o;
}

// ===========================================================================
// FP16 mma.sync GEMM (NT): C = scale*(A[M,K] @ B[N,K]^T)
// 128x128x64 block tile, 4 warps (2x2), warp 64x64, 2 CTA/SM,
// 3-stage cp.async ring, SW128 swizzle, ldmatrix, m16n8k16 fp32-acc.
//   ybase:   row-block offset (m0 = (ybase + yb) * 128) for row-range halves
//   CAUSAL:  skip blocks above diagonal; DIAGONAL blocks write NEG_BIG
//   CAPK:    cap k-loop at m0+128 (PV); reverses y-order within the half
//   OUTH:    fp16 output; else fp32
//   KSPLIT>0: split capped k-range across blockIdx.z -> Cf + z*M*ldc;
//            z==0 partial adds residual res (if non-null)
//   QKV:     blockIdx.z in {0,1} selects weight B+z*D*D and output {Ch,C2h};
//            z==0 applies scale (Q/sqrt(d))
//   TRANSC:  write OUTPUT TRANSPOSED fp16 (C[n][m], row stride ldct)
// ===========================================================================
#define BK 64
#define TILE_B (128 * 128)       // 16 KB per tile buffer
#define NSTAGE 3
#define SM_A 0
#define SM_B (NSTAGE * TILE_B)
#define SM_TOT (2 * NSTAGE * TILE_B)   // 96 KB

template<int CAUSAL, int CAPK, int OUTH, int KSPLIT, int QKV, int TRANSC>
__global__ void __launch_bounds__(128, 2)
gemm_f16(const __half* __restrict__ A,
         const __half* __restrict__ B,
         __half* __restrict__ Ch,
         __half* __restrict__ C2h,
         float* __restrict__ Cf,
         const float* __restrict__ res,
         int M, int N, int K,
         int lda, int ldb, int ldc, int ldct,
         float scale, int ybase)
{
    extern __shared__ char smem[];
    int yb = CAPK ? ((int)gridDim.y - 1 - (int)blockIdx.y) : (int)blockIdx.y;
    int m0 = (ybase + yb) * 128;
    int n0 = blockIdx.x * 128;
    if (CAUSAL && n0 > m0 + 127) return;

    const __half* Bp = B;
    __half* Chp = Ch;
    float* Cfp = Cf;
    int ldcw = ldc;
    float sc = scale;
    if (QKV) {
        int zq = blockIdx.z;
        Bp = B + (size_t)zq * D_DIM * D_DIM;
        Chp = (zq == 0) ? Ch : C2h;
        if (zq != 0) sc = 1.0f;       // scale only applies to Q
    }
    if (TRANSC) ldcw = ldct;

    uint32_t sbase = smem_u32(smem);
    int t    = threadIdx.x;
    int lane = t & 31;
    int warp = t >> 5;
    int gid  = lane >> 2;
    int tig  = lane & 3;
    int wm   = (warp >> 1) * 64;
    int wn   = (warp & 1) * 64;

    int kend  = CAPK ? min(K, m0 + 128) : K;
    int iters = kend / BK;
    int it0 = 0, it1 = iters;
    if (KSPLIT > 0) {
        int z = blockIdx.z;
        it0 = (iters * z) / KSPLIT;
        it1 = (iters * (z + 1)) / KSPLIT;
        Cfp = Cf + (size_t)z * M * ldc;
    }
    int niter = it1 - it0;

    auto load_tiles = [&](int buf, int k0) {
        #pragma unroll
        for (int i = 0; i < 8; i++) {
            int f = t + i * 128;
            int row = f >> 3, kg = f & 7;
            uint32_t off = SW128((uint32_t)(row * 128 + kg * 16));
            CP_ASYNC16(sbase + SM_A + buf * TILE_B + off,
                       A + (size_t)(m0 + row) * lda + k0 + kg * 8);
        }
        #pragma unroll
        for (int i = 0; i < 8; i++) {
            int f = t + i * 128;
            int row = f >> 3, kg = f & 7;
            uint32_t off = SW128((uint32_t)(row * 128 + kg * 16));
            CP_ASYNC16(sbase + SM_B + buf * TILE_B + off,
                       Bp + (size_t)(n0 + row) * ldb + k0 + kg * 8);
        }
    };

    float acc[4][8][4];
    #pragma unroll
    for (int mi = 0; mi < 4; mi++)
        #pragma unroll
        for (int ni = 0; ni < 8; ni++)
            #pragma unroll
            for (int r = 0; r < 4; r++) acc[mi][ni][r] = 0.0f;

    int q   = lane >> 3;
    int r8  = lane & 7;
    int aq1 = (q & 1) * 8;
    int aq2 = q >> 1;
    int bq1 = (q >> 1) * 8;
    int bq2 = q & 1;

    load_tiles(0, it0 * BK);
    CP_COMMIT();
    if (niter > 1) load_tiles(1, (it0 + 1) * BK);
    CP_COMMIT();

    int buf = 0;
    for (int it = 0; it < niter; it++) {
        CP_WAIT1();
        __syncthreads();

        uint32_t sa = sbase + SM_A + buf * TILE_B;
        uint32_t sb = sbase + SM_B + buf * TILE_B;

        int nx = it + 2;
        int nbuf = buf + 2; if (nbuf >= NSTAGE) nbuf -= NSTAGE;
        if (nx < niter) load_tiles(nbuf, (it0 + nx) * BK);
        CP_COMMIT();

        #pragma unroll
        for (int ks = 0; ks < BK / 16; ks++) {
            uint32_t afr[4][4];
            #pragma unroll
            for (int mi = 0; mi < 4; mi++) {
                int row = wm + mi * 16 + aq1 + r8;
                int kg  = 2 * ks + aq2;
                uint32_t addr = sa + (uint32_t)(row * 128) + (uint32_t)((kg ^ r8) * 16);
                ldsm_x4(afr[mi][0], afr[mi][1], afr[mi][2], afr[mi][3], addr);
            }
            uint32_t bfr[8][2];
            #pragma unroll
            for (int p = 0; p < 4; p++) {
                int row = wn + p * 16 + bq1 + r8;
                int kg  = 2 * ks + bq2;
                uint32_t addr = sb + (uint32_t)(row * 128) + (uint32_t)((kg ^ r8) * 16);
                uint32_t r0, r1, r2, r3;
                ldsm_x4(r0, r1, r2, r3, addr);
                bfr[2 * p][0] = r0; bfr[2 * p][1] = r1;
                bfr[2 * p + 1][0] = r2; bfr[2 * p + 1][1] = r3;
            }
            #pragma unroll
            for (int mi = 0; mi < 4; mi++)
                #pragma unroll
                for (int ni = 0; ni < 8; ni++)
                    mma_f16(acc[mi][ni], afr[mi], bfr[ni]);
        }

        buf++; if (buf >= NSTAGE) buf = 0;
    }

    if (TRANSC) {
        // Transposed fp16 output (vt)
        __syncthreads();
        float* st = (float*)smem;        // 128 x stride 132
        #pragma unroll
        for (int mi = 0; mi < 4; mi++) {
            #pragma unroll
            for (int ni = 0; ni < 8; ni++) {
                int row = wm + mi * 16 + gid;
                int col = wn + ni * 8 + tig * 2;
                st[(col + 0) * 132 + row]     = acc[mi][ni][0];
                st[(col + 1) * 132 + row]     = acc[mi][ni][1];
                st[(col + 0) * 132 + row + 8] = acc[mi][ni][2];
                st[(col + 1) * 132 + row + 8] = acc[mi][ni][3];
            }
        }
        __syncthreads();
        #pragma unroll
        for (int i = 0; i < 16; i++) {
            int idx = t + i * 128;
            int d = idx >> 4;
            int j = idx & 15;
            const float* sp = &st[d * 132 + j * 8];
            uint4 u;
            u.x = pack_h2(sp[0], sp[1]);
            u.y = pack_h2(sp[2], sp[3]);
            u.z = pack_h2(sp[4], sp[5]);
            u.w = pack_h2(sp[6], sp[7]);
            *(uint4*)(Chp + (size_t)(n0 + d) * ldcw + m0 + j * 8) = u;
        }
        return;
    }

    if (OUTH) {
        // fp16 output; on CAUSAL diagonal blocks, mask col>row with NEG_BIG
        bool diag = CAUSAL && (n0 == m0);
        #pragma unroll
        for (int mi = 0; mi < 4; mi++) {
            #pragma unroll
            for (int ni = 0; ni < 8; ni++) {
                int row = m0 + wm + mi * 16 + gid;
                int col = n0 + wn + ni * 8 + tig * 2;
                float v00 = acc[mi][ni][0] * sc;
                float v01 = acc[mi][ni][1] * sc;
                float v10 = acc[mi][ni][2] * sc;
                float v11 = acc[mi][ni][3] * sc;
                if (diag) {
                    if (col > row)         v00 = NEG_BIG;
                    if (col + 1 > row)     v01 = NEG_BIG;
                    if (col > row + 8)     v10 = NEG_BIG;
                    if (col + 1 > row + 8) v11 = NEG_BIG;
                }
                *(uint32_t*)(Chp + (size_t)row * ldcw + col)       = pack_h2(v00, v01);
                *(uint32_t*)(Chp + (size_t)(row + 8) * ldcw + col) = pack_h2(v10, v11);
            }
        }
        return;
    }

    // fp32 output (PV partials, raw; z=0 adds residual)
    bool addres = (KSPLIT > 0) && (blockIdx.z == 0) && (res != nullptr);
    #pragma unroll
    for (int mi = 0; mi < 4; mi++) {
        #pragma unroll
        for (int ni = 0; ni < 8; ni++) {
            int row = m0 + wm + mi * 16 + gid;
            int col = n0 + wn + ni * 8 + tig * 2;
            float2 o0, o1;
            o0.x = acc[mi][ni][0]; o0.y = acc[mi][ni][1];
            o1.x = acc[mi][ni][2]; o1.y = acc[mi][ni][3];
            size_t i0 = (size_t)row * ldcw + col;
            size_t i1 = (size_t)(row + 8) * ldcw + col;
            if (addres) {
                float2 r0 = *(const float2*)(res + i0);
                float2 r1 = *(const float2*)(res + i1);
                o0.x += r0.x; o0.y += r0.y;
                o1.x += r1.x; o1.y += r1.y;
            }
            *(float2*)(Cfp + i0) = o0;
            *(float2*)(Cfp + i1) = o1;
        }
    }
}

// ===========================================================================
// Causal row softmax over fp16 S (in place), SINGLE PASS with constant shift.
// Masked entries are NEG_BIG -> exp underflows to exact 0. rowbase offsets
// the row index for half-range launches.
// ===========================================================================
__device__ __forceinline__ float block_reduce_sum(float v)
{
    __shared__ float sm[8];
    #pragma unroll
    for (int o = 16; o; o >>= 1)
        v += __shfl_xor_sync(0xffffffffu, v, o);
    int lane = threadIdx.x & 31, warp = threadIdx.x >> 5;
    if (lane == 0) sm[warp] = v;
    __syncthreads();
    float r = sm[0];
    #pragma unroll
    for (int i = 1; i < 8; i++) r += sm[i];
    return r;
}

__global__ void softmax_causal(__half* __restrict__ S, int rowbase)
{
    int row = rowbase + blockIdx.x;
    int t = threadIdx.x;                 // 0..255
    int zend = (row & ~127) + 128;       // zero-pad cap (= PV k-cap)
    uint4* Srow = (uint4*)(S + (size_t)row * T_DIM);   // 8 halves per uint4

    float x[4][8];
    float sum = 0.0f;
    #pragma unroll
    for (int it = 0; it < 4; it++) {
        int j0 = (it << 11) + t * 8;
        bool grp = (j0 < zend);          // group-uniform
        uint4 u = make_uint4(0, 0, 0, 0);
        if (grp) u = Srow[(it << 8) + t];
        float2 f0 = __half22float2(*(__half2*)&u.x);
        float2 f1 = __half22float2(*(__half2*)&u.y);
        float2 f2 = __half22float2(*(__half2*)&u.z);
        float2 f3 = __half22float2(*(__half2*)&u.w);
        x[it][0] = __expf((grp ? f0.x : NEG_BIG) - SM_SHIFT);
        x[it][1] = __expf((grp ? f0.y : NEG_BIG) - SM_SHIFT);
        x[it][2] = __expf((grp ? f1.x : NEG_BIG) - SM_SHIFT);
        x[it][3] = __expf((grp ? f1.y : NEG_BIG) - SM_SHIFT);
        x[it][4] = __expf((grp ? f2.x : NEG_BIG) - SM_SHIFT);
        x[it][5] = __expf((grp ? f2.y : NEG_BIG) - SM_SHIFT);
        x[it][6] = __expf((grp ? f3.x : NEG_BIG) - SM_SHIFT);
        x[it][7] = __expf((grp ? f3.y : NEG_BIG) - SM_SHIFT);
        #pragma unroll
        for (int e = 0; e < 8; e++) sum += x[it][e];
    }
    sum = block_reduce_sum(sum);
    float inv = 1.0f / sum;

    #pragma unroll
    for (int it = 0; it < 4; it++) {
        int j0 = (it << 11) + t * 8;
        if (j0 < zend) {
            uint4 u;
            u.x = pack_h2(x[it][0] * inv, x[it][1] * inv);
            u.y = pack_h2(x[it][2] * inv, x[it][3] * inv);
            u.z = pack_h2(x[it][4] * inv, x[it][5] * inv);
            u.w = pack_h2(x[it][6] * inv, x[it][7] * inv);
            Srow[(it << 8) + t] = u;
        }
    }
}

// ===========================================================================
extern "C" void kernel_launch(void* const* d_in, const int* in_sizes, int n_in,
                              void* d_out, int out_size)
{
    const float* h    = (const float*)d_in[0];
    const float* ln_w = (const float*)d_in[1];
    const float* ln_b = (const float*)d_in[2];
    const float* w_q  = (const float*)d_in[3];
    const float* w_k  = (const float*)d_in[4];
    const float* w_v  = (const float*)d_in[5];
    const float* w_o  = (const float*)d_in[6];
    float* out = (float*)d_out;

    __half *hn, *q, *k, *vt, *S, *wr, *wvt;
    float *avp;
    cudaGetSymbolAddress((void**)&hn,  g_hnorm);
    cudaGetSymbolAddress((void**)&q,   g_q);
    cudaGetSymbolAddress((void**)&k,   g_k);
    cudaGetSymbolAddress((void**)&vt,  g_vt);
    cudaGetSymbolAddress((void**)&avp, g_avp);
    cudaGetSymbolAddress((void**)&S,   g_S);
    cudaGetSymbolAddress((void**)&wr,  g_wr);
    cudaGetSymbolAddress((void**)&wvt, g_wvt);
    __half* wp_r = wr + 2 * (size_t)D_DIM * D_DIM;   // W' slot
    __half* wo_r = wr + 3 * (size_t)D_DIM * D_DIM;   // Wo slot

    // One-time host-side resources (created on the correctness call, reused
    // under graph capture; device work identical every call).
    static cudaStream_t s2 = nullptr, s3 = nullptr;
    static cudaEvent_t ev_fork = nullptr, ev_vt = nullptr,
                       ev_qk = nullptr, ev_b = nullptr;
    if (s2 == nullptr) {
        cudaStreamCreateWithFlags(&s2, cudaStreamNonBlocking);
        cudaStreamCreateWithFlags(&s3, cudaStreamNonBlocking);
        cudaEventCreateWithFlags(&ev_fork, cudaEventDisableTiming);
        cudaEventCreateWithFlags(&ev_vt,   cudaEventDisableTiming);
        cudaEventCreateWithFlags(&ev_qk,   cudaEventDisableTiming);
        cudaEventCreateWithFlags(&ev_b,    cudaEventDisableTiming);
    }

    cudaFuncSetAttribute((const void*)gemm_f16<0,0,1,0,1,0>,
                         cudaFuncAttributeMaxDynamicSharedMemorySize, SM_TOT);
    cudaFuncSetAttribute((const void*)gemm_f16<0,0,1,0,0,1>,
                         cudaFuncAttributeMaxDynamicSharedMemorySize, SM_TOT);
    cudaFuncSetAttribute((const void*)gemm_f16<1,0,1,0,0,0>,
                         cudaFuncAttributeMaxDynamicSharedMemorySize, SM_TOT);
    cudaFuncSetAttribute((const void*)gemm_f16<0,1,0,4,0,0>,
                         cudaFuncAttributeMaxDynamicSharedMemorySize, SM_TOT);
    cudaFuncSetAttribute((const void*)gemm_f16<0,0,1,0,0,0>,
                         cudaFuncAttributeMaxDynamicSharedMemorySize, SM_TOT);

    const float inv_sqrt_d = 0.044194173824159216f;  // 1/sqrt(512)
    const int NB = T_DIM / 128;          // 64 row blocks
    const int RA = RSPLIT;               // half A blocks [0, RA)
    const int RB = NB - RA;              // half B blocks [RA, 64)
    const int rowsA = RA * 128;          // 5760
    const int rowsB = T_DIM - rowsA;     // 2432

    // 1) LayerNorm -> fp16 (+ fused fp16 weight rounding into g_wr)
    ln_kernel<<<T_DIM, 128>>>(h, ln_w, ln_b, hn, w_q, w_k, w_v, w_o, wr);

    // ---- fork: s2 computes Wv^T -> W' -> V'^T while main runs QK etc. ----
    cudaEventRecord(ev_fork, 0);
    cudaStreamWaitEvent(s2, ev_fork, 0);

    dim3 gT(D_DIM / 32, D_DIM / 32);
    wv_transpose<<<gT, 256, 0, s2>>>(w_v, wvt);

    dim3 gWp(D_DIM / 128, D_DIM / 128);
    gemm_f16<0,0,1,0,0,0><<<gWp, 128, SM_TOT, s2>>>(wo_r, wvt,
        wp_r, nullptr, nullptr, nullptr,
        D_DIM, D_DIM, D_DIM, D_DIM, D_DIM, D_DIM, 0, 1.0f, 0);

    dim3 gVp(D_DIM / 128, T_DIM / 128);
    gemm_f16<0,0,1,0,0,1><<<gVp, 128, SM_TOT, s2>>>(hn, wp_r,
        vt, nullptr, nullptr, nullptr,
        T_DIM, D_DIM, D_DIM, D_DIM, D_DIM, 0, T_DIM, 1.0f, 0);
    cudaEventRecord(ev_vt, s2);

    // main: Q (pre-scaled) and K projections
    dim3 gQK(D_DIM / 128, T_DIM / 128, 2);
    gemm_f16<0,0,1,0,1,0><<<gQK, 128, SM_TOT>>>(hn, wr,
        q, k, nullptr, nullptr,
        T_DIM, D_DIM, D_DIM, D_DIM, D_DIM, D_DIM, 0, inv_sqrt_d, 0);
    cudaEventRecord(ev_qk, 0);

    // ---- fork half B onto s3 ----
    cudaStreamWaitEvent(s3, ev_qk, 0);

    // === half A on stream 0 ===
    dim3 gScoreA(NB, RA);
    gemm_f16<1,0,1,0,0,0><<<gScoreA, 128, SM_TOT>>>(q, k,
        S, nullptr, nullptr, nullptr,
        T_DIM, T_DIM, D_DIM, D_DIM, D_DIM, T_DIM, 0, 1.0f, 0);
    softmax_causal<<<rowsA, 256>>>(S, 0);
    cudaStreamWaitEvent(0, ev_vt, 0);
    dim3 gPVA(D_DIM / 128, RA, 4);
    gemm_f16<0,1,0,4,0,0><<<gPVA, 128, SM_TOT>>>(S, vt,
        nullptr, nullptr, avp, h,
        T_DIM, D_DIM, T_DIM, T_DIM, T_DIM, D_DIM, 0, 1.0f, 0);
    reduce_out<<<rowsA * (D_DIM / 4) / 256, 256>>>(avp, out, 0);

    // === half B on stream s3 ===
    dim3 gScoreB(NB, RB);
    gemm_f16<1,0,1,0,0,0><<<gScoreB, 128, SM_TOT, s3>>>(q, k,
        S, nullptr, nullptr, nullptr,
        T_DIM, T_DIM, D_DIM, D_DIM, D_DIM, T_DIM, 0, 1.0f, RA);
    softmax_causal<<<rowsB, 256, 0, s3>>>(S, rowsA);
    cudaStreamWaitEvent(s3, ev_vt, 0);
    dim3 gPVB(D_DIM / 128, RB, 4);
    gemm_f16<0,1,0,4,0,0><<<gPVB, 128, SM_TOT, s3>>>(S, vt,
        nullptr, nullptr, avp, h,
        T_DIM, D_DIM, T_DIM, T_DIM, T_DIM, D_DIM, 0, 1.0f, RA);
    reduce_out<<<rowsB * (D_DIM / 4) / 256, 256, 0, s3>>>(avp, out,
        rowsA * (D_DIM / 4));
    cudaEventRecord(ev_b, s3);

    // join half B back into the origin stream before capture end
    cudaStreamWaitEvent(0, ev_b, 0);
}